// round 3
// baseline (speedup 1.0000x reference)
#include <cuda_runtime.h>

#define NROWS (1 << 20)

// ---- device-global scratch ----
__device__ float g_acc1[32];    // [0:16) sum, [16:32) sumsq of relu(conv1)
__device__ float g_acc2[64];    // [0:32) sum, [32:64) sumsq of relu(conv2)
__device__ float g_w2f[96];     // BN1-folded conv2 weights  [oc*3 + k]
__device__ float g_d2[96];      // folded conv2 bias table   [oc*3 + t]
__device__ float g_fw1t[512];   // BN2+mean-folded fc1 weights TRANSPOSED [oc*16 + j]
__device__ float g_fb1f[16];    // folded fc1 bias

__global__ void zero_kernel() {
    int t = threadIdx.x;
    if (t < 32) g_acc1[t] = 0.f;
    if (t < 64) g_acc2[t] = 0.f;
}

// ---------------- pass 1: stats of relu(conv1(x)+b1) ----------------
__global__ void __launch_bounds__(256) pass1_kernel(const float* __restrict__ x,
                                                    const float* __restrict__ w1,
                                                    const float* __restrict__ b1) {
    __shared__ float sw[48], sb[16];
    __shared__ float red[8 * 32];
    int tid = threadIdx.x;
    if (tid < 48) sw[tid] = w1[tid];
    if (tid < 16) sb[tid] = b1[tid];
    __syncthreads();

    float acc[32];
#pragma unroll
    for (int i = 0; i < 32; i++) acc[i] = 0.f;

    int stride = gridDim.x * blockDim.x;
#pragma unroll 1
    for (int row = blockIdx.x * blockDim.x + tid; row < NROWS; row += stride) {
        float x0 = x[3*row], x1v = x[3*row+1], x2 = x[3*row+2];
#pragma unroll
        for (int c = 0; c < 16; c++) {
            float wa = sw[3*c], wb = sw[3*c+1], wc = sw[3*c+2], bias = sb[c];
            float h0 = fmaxf(fmaf(wb, x0, fmaf(wc, x1v, bias)), 0.f);
            float h1 = fmaxf(fmaf(wa, x0, fmaf(wb, x1v, fmaf(wc, x2, bias))), 0.f);
            float h2 = fmaxf(fmaf(wa, x1v, fmaf(wb, x2, bias)), 0.f);
            acc[c]      += h0 + h1 + h2;
            acc[16 + c] += h0*h0 + h1*h1 + h2*h2;
        }
    }

    int lane = tid & 31, warp = tid >> 5;
#pragma unroll
    for (int i = 0; i < 32; i++) {
        float v = acc[i];
#pragma unroll
        for (int o = 16; o; o >>= 1) v += __shfl_down_sync(0xffffffffu, v, o);
        if (lane == 0) red[warp * 32 + i] = v;
    }
    __syncthreads();
    if (tid < 32) {
        float v = 0.f;
#pragma unroll
        for (int w = 0; w < 8; w++) v += red[w * 32 + tid];
        atomicAdd(&g_acc1[tid], v);
    }
}

// ------------- finalize 1: BN1 params, fold into conv2 -------------
__global__ void finalize1_kernel(const float* __restrict__ g1, const float* __restrict__ bt1,
                                 const float* __restrict__ w2, const float* __restrict__ b2) {
    __shared__ float a1s[16], c1s[16];
    int t = threadIdx.x;
    const float inv = 1.f / (3.f * (float)NROWS);
    if (t < 16) {
        float m   = g_acc1[t] * inv;
        float var = g_acc1[16 + t] * inv - m * m;
        float a   = g1[t] * rsqrtf(var + 1e-5f);
        a1s[t] = a;
        c1s[t] = bt1[t] - m * a;
    }
    __syncthreads();
    if (t < 32) {
        int ic = t >> 1;
        float a = a1s[ic], c = c1s[ic];
        float w0 = w2[3*t], wb = w2[3*t+1], wc = w2[3*t+2];
        g_w2f[3*t+0] = w0 * a;
        g_w2f[3*t+1] = wb * a;
        g_w2f[3*t+2] = wc * a;
        float bb = b2[t];
        g_d2[3*t+0] = bb + c * (wb + wc);        // t=0: taps k=1,2 in-bounds
        g_d2[3*t+1] = bb + c * (w0 + wb + wc);   // t=1: all taps
        g_d2[3*t+2] = bb + c * (w0 + wb);        // t=2: taps k=0,1 in-bounds
    }
}

// ------- pass 2: stats of relu(conv2(bn1)+b2); blockIdx.y picks channel half -------
__global__ void __launch_bounds__(256) pass2_kernel(const float* __restrict__ x,
                                                    const float* __restrict__ w1,
                                                    const float* __restrict__ b1) {
    __shared__ float sw[48], sb[16], sw2[96], sd2[96];
    __shared__ float red[8 * 32];
    int tid = threadIdx.x;
    int half = blockIdx.y;          // 0 or 1
    if (tid < 48) sw[tid] = w1[tid];
    if (tid < 16) sb[tid] = b1[tid];
    if (tid < 96) { sw2[tid] = g_w2f[tid]; sd2[tid] = g_d2[tid]; }
    __syncthreads();

    const int ic0 = 8 * half;       // input channels [ic0, ic0+8)
    float acc[32];                  // [0:16) sum, [16:32) sumsq for oc = 16*half + j
#pragma unroll
    for (int i = 0; i < 32; i++) acc[i] = 0.f;

    int stride = gridDim.x * blockDim.x;
#pragma unroll 1
    for (int row = blockIdx.x * blockDim.x + tid; row < NROWS; row += stride) {
        float x0 = x[3*row], x1v = x[3*row+1], x2 = x[3*row+2];
#pragma unroll
        for (int i = 0; i < 8; i++) {
            int ic = ic0 + i;
            float wa = sw[3*ic], wb = sw[3*ic+1], wc = sw[3*ic+2], bias = sb[ic];
            float h0 = fmaxf(fmaf(wb, x0, fmaf(wc, x1v, bias)), 0.f);
            float h1 = fmaxf(fmaf(wa, x0, fmaf(wb, x1v, fmaf(wc, x2, bias))), 0.f);
            float h2 = fmaxf(fmaf(wa, x1v, fmaf(wb, x2, bias)), 0.f);
#pragma unroll
            for (int d = 0; d < 2; d++) {
                int oc = 2*ic + d;          // in [16*half, 16*half+16)
                int j  = 2*i + d;           // local accumulator index 0..15
                float u0 = sw2[3*oc], ub = sw2[3*oc+1], uc = sw2[3*oc+2];
                float t0 = fmaxf(fmaf(ub, h0, fmaf(uc, h1, sd2[3*oc+0])), 0.f);
                float t1 = fmaxf(fmaf(u0, h0, fmaf(ub, h1,
                                 fmaf(uc, h2, sd2[3*oc+1]))), 0.f);
                float t2 = fmaxf(fmaf(u0, h1, fmaf(ub, h2, sd2[3*oc+2])), 0.f);
                acc[j]      += t0 + t1 + t2;
                acc[16 + j] += t0*t0 + t1*t1 + t2*t2;
            }
        }
    }

    int lane = tid & 31, warp = tid >> 5;
#pragma unroll
    for (int i = 0; i < 32; i++) {
        float v = acc[i];
#pragma unroll
        for (int o = 16; o; o >>= 1) v += __shfl_down_sync(0xffffffffu, v, o);
        if (lane == 0) red[warp * 32 + i] = v;
    }
    __syncthreads();
    if (tid < 32) {
        float v = 0.f;
#pragma unroll
        for (int w = 0; w < 8; w++) v += red[w * 32 + tid];
        int base = 16 * half;
        if (tid < 16) atomicAdd(&g_acc2[base + tid], v);
        else          atomicAdd(&g_acc2[32 + base + (tid - 16)], v);
    }
}

// ------- finalize 2: BN2 params, fold (BN2 + mean/3) into FC1 (transposed) -------
__global__ void finalize2_kernel(const float* __restrict__ g2, const float* __restrict__ bt2,
                                 const float* __restrict__ fw1, const float* __restrict__ fb1) {
    __shared__ float a2s[32], c2s[32];   // a2s holds a2/3
    int t = threadIdx.x;  // 512 threads
    const float inv = 1.f / (3.f * (float)NROWS);
    if (t < 32) {
        float m   = g_acc2[t] * inv;
        float var = g_acc2[32 + t] * inv - m * m;
        float a   = g2[t] * rsqrtf(var + 1e-5f);
        a2s[t] = a * (1.f / 3.f);
        c2s[t] = bt2[t] - m * a;
    }
    __syncthreads();
    int oc = t >> 4, j = t & 15;
    g_fw1t[t] = fw1[j * 32 + oc] * a2s[oc];   // transposed: [oc][j]
    if (t < 16) {
        float s = fb1[t];
#pragma unroll
        for (int c = 0; c < 32; c++) s = fmaf(fw1[t*32 + c], c2s[c], s);
        g_fb1f[t] = s;
    }
}

// ---------------- pass 3: full fused forward ----------------
__global__ void __launch_bounds__(256) pass3_kernel(const float* __restrict__ x,
                                                    const float* __restrict__ w1,
                                                    const float* __restrict__ b1,
                                                    const float* __restrict__ fw2,
                                                    const float* __restrict__ fb2,
                                                    float* __restrict__ out) {
    __shared__ float sw[48], sb[16], sw2[96], sd2[96];
    __shared__ __align__(16) float sfw1t[512];
    __shared__ float sfb1[16], sfw2[16];
    int tid = threadIdx.x;
    if (tid < 48) sw[tid] = w1[tid];
    if (tid < 16) { sb[tid] = b1[tid]; sfb1[tid] = g_fb1f[tid]; sfw2[tid] = fw2[tid]; }
    if (tid < 96) { sw2[tid] = g_w2f[tid]; sd2[tid] = g_d2[tid]; }
    for (int i = tid; i < 512; i += blockDim.x) sfw1t[i] = g_fw1t[i];
    __syncthreads();
    const float fb2v = fb2[0];

    int stride = gridDim.x * blockDim.x;
#pragma unroll 1
    for (int row = blockIdx.x * blockDim.x + tid; row < NROWS; row += stride) {
        float x0 = x[3*row], x1v = x[3*row+1], x2 = x[3*row+2];
        float f[16];
#pragma unroll
        for (int j = 0; j < 16; j++) f[j] = sfb1[j];

#pragma unroll
        for (int ic = 0; ic < 16; ic++) {
            float wa = sw[3*ic], wb = sw[3*ic+1], wc = sw[3*ic+2], bias = sb[ic];
            float h0 = fmaxf(fmaf(wb, x0, fmaf(wc, x1v, bias)), 0.f);
            float h1 = fmaxf(fmaf(wa, x0, fmaf(wb, x1v, fmaf(wc, x2, bias))), 0.f);
            float h2 = fmaxf(fmaf(wa, x1v, fmaf(wb, x2, bias)), 0.f);
#pragma unroll
            for (int d = 0; d < 2; d++) {
                int oc = 2*ic + d;
                float u0 = sw2[3*oc], ub = sw2[3*oc+1], uc = sw2[3*oc+2];
                float t0 = fmaxf(fmaf(ub, h0, fmaf(uc, h1, sd2[3*oc+0])), 0.f);
                float t1 = fmaxf(fmaf(u0, h0, fmaf(ub, h1,
                                 fmaf(uc, h2, sd2[3*oc+1]))), 0.f);
                float t2 = fmaxf(fmaf(u0, h1, fmaf(ub, h2, sd2[3*oc+2])), 0.f);
                float s = t0 + t1 + t2;   // pooled (pre-BN2 scale) channel sum
#pragma unroll
                for (int q4 = 0; q4 < 4; q4++) {
                    float4 w = *reinterpret_cast<const float4*>(&sfw1t[oc*16 + 4*q4]);
                    f[4*q4 + 0] = fmaf(w.x, s, f[4*q4 + 0]);
                    f[4*q4 + 1] = fmaf(w.y, s, f[4*q4 + 1]);
                    f[4*q4 + 2] = fmaf(w.z, s, f[4*q4 + 2]);
                    f[4*q4 + 3] = fmaf(w.w, s, f[4*q4 + 3]);
                }
            }
        }
        float o = fb2v;
#pragma unroll
        for (int j = 0; j < 16; j++) o = fmaf(sfw2[j], fmaxf(f[j], 0.f), o);
        out[row] = o;
    }
}

extern "C" void kernel_launch(void* const* d_in, const int* in_sizes, int n_in,
                              void* d_out, int out_size) {
    const float* x   = (const float*)d_in[0];
    const float* w1  = (const float*)d_in[1];
    const float* b1  = (const float*)d_in[2];
    const float* g1  = (const float*)d_in[3];
    const float* bt1 = (const float*)d_in[4];
    const float* w2  = (const float*)d_in[5];
    const float* b2  = (const float*)d_in[6];
    const float* g2  = (const float*)d_in[7];
    const float* bt2 = (const float*)d_in[8];
    const float* fw1 = (const float*)d_in[9];
    const float* fb1 = (const float*)d_in[10];
    const float* fw2 = (const float*)d_in[11];
    const float* fb2 = (const float*)d_in[12];
    float* out = (float*)d_out;

    zero_kernel<<<1, 64>>>();
    pass1_kernel<<<1024, 256>>>(x, w1, b1);
    finalize1_kernel<<<1, 32>>>(g1, bt1, w2, b2);
    dim3 g2d(1024, 2);
    pass2_kernel<<<g2d, 256>>>(x, w1, b1);
    finalize2_kernel<<<1, 512>>>(g2, bt2, fw1, fb1);
    pass3_kernel<<<1024, 256>>>(x, w1, b1, fw2, fb2, out);
}

// round 4
// speedup vs baseline: 6.2447x; 6.2447x over previous
#include <cuda_runtime.h>

#define NROWS (1 << 20)

// ---- device-global scratch ----
__device__ float g_acc1[32];    // [0:16) sum, [16:32) sumsq of relu(conv1)
__device__ float g_acc2[64];    // [0:32) sum, [32:64) sumsq of relu(conv2)
__device__ float g_w2f[96];     // BN1-folded conv2 weights  [oc*3 + k]
__device__ float g_d2[96];      // folded conv2 bias table   [oc*3 + t]
__device__ float g_fw1f[512];   // BN2+mean-folded fc1 weights [j*32 + oc]
__device__ float g_fb1f[16];    // folded fc1 bias

__global__ void zero_kernel() {
    int t = threadIdx.x;
    if (t < 32) g_acc1[t] = 0.f;
    if (t < 64) g_acc2[t] = 0.f;
}

// ---------------- pass 1: stats of relu(conv1(x)+b1) ----------------
__global__ void __launch_bounds__(256) pass1_kernel(const float* __restrict__ x,
                                                    const float* __restrict__ w1,
                                                    const float* __restrict__ b1) {
    __shared__ float sw[48], sb[16];
    __shared__ float red[8 * 32];
    int tid = threadIdx.x;
    if (tid < 48) sw[tid] = w1[tid];
    if (tid < 16) sb[tid] = b1[tid];
    __syncthreads();

    float acc[32];
#pragma unroll
    for (int i = 0; i < 32; i++) acc[i] = 0.f;

    int stride = gridDim.x * blockDim.x;
#pragma unroll 1
    for (int row = blockIdx.x * blockDim.x + tid; row < NROWS; row += stride) {
        float x0 = x[3*row], x1v = x[3*row+1], x2 = x[3*row+2];
#pragma unroll
        for (int c = 0; c < 16; c++) {
            float wa = sw[3*c], wb = sw[3*c+1], wc = sw[3*c+2], bias = sb[c];
            float h0 = fmaxf(fmaf(wb, x0, fmaf(wc, x1v, bias)), 0.f);
            float h1 = fmaxf(fmaf(wa, x0, fmaf(wb, x1v, fmaf(wc, x2, bias))), 0.f);
            float h2 = fmaxf(fmaf(wa, x1v, fmaf(wb, x2, bias)), 0.f);
            acc[c]      += h0 + h1 + h2;
            acc[16 + c] += h0*h0 + h1*h1 + h2*h2;
        }
    }

    int lane = tid & 31, warp = tid >> 5;
#pragma unroll
    for (int i = 0; i < 32; i++) {
        float v = acc[i];
#pragma unroll
        for (int o = 16; o; o >>= 1) v += __shfl_down_sync(0xffffffffu, v, o);
        if (lane == 0) red[warp * 32 + i] = v;
    }
    __syncthreads();
    if (tid < 32) {
        float v = 0.f;
#pragma unroll
        for (int w = 0; w < 8; w++) v += red[w * 32 + tid];
        atomicAdd(&g_acc1[tid], v);
    }
}

// ------------- finalize 1: BN1 params, fold into conv2 -------------
__global__ void finalize1_kernel(const float* __restrict__ g1, const float* __restrict__ bt1,
                                 const float* __restrict__ w2, const float* __restrict__ b2) {
    __shared__ float a1s[16], c1s[16];
    int t = threadIdx.x;
    const float inv = 1.f / (3.f * (float)NROWS);
    if (t < 16) {
        float m   = g_acc1[t] * inv;
        float var = g_acc1[16 + t] * inv - m * m;
        float a   = g1[t] * rsqrtf(var + 1e-5f);
        a1s[t] = a;
        c1s[t] = bt1[t] - m * a;
    }
    __syncthreads();
    if (t < 32) {
        int ic = t >> 1;
        float a = a1s[ic], c = c1s[ic];
        float w0 = w2[3*t], wb = w2[3*t+1], wc = w2[3*t+2];
        g_w2f[3*t+0] = w0 * a;
        g_w2f[3*t+1] = wb * a;
        g_w2f[3*t+2] = wc * a;
        float bb = b2[t];
        g_d2[3*t+0] = bb + c * (wb + wc);        // t=0: taps k=1,2 in-bounds
        g_d2[3*t+1] = bb + c * (w0 + wb + wc);   // t=1: all taps
        g_d2[3*t+2] = bb + c * (w0 + wb);        // t=2: taps k=0,1 in-bounds
    }
}

// ------- pass 2: stats of relu(conv2(bn1)+b2); blockIdx.y picks channel half -------
__global__ void __launch_bounds__(256) pass2_kernel(const float* __restrict__ x,
                                                    const float* __restrict__ w1,
                                                    const float* __restrict__ b1) {
    __shared__ float sw[48], sb[16], sw2[96], sd2[96];
    __shared__ float red[8 * 32];
    int tid = threadIdx.x;
    int half = blockIdx.y;          // 0 or 1
    if (tid < 48) sw[tid] = w1[tid];
    if (tid < 16) sb[tid] = b1[tid];
    if (tid < 96) { sw2[tid] = g_w2f[tid]; sd2[tid] = g_d2[tid]; }
    __syncthreads();

    const int ic0 = 8 * half;       // input channels [ic0, ic0+8)
    float acc[32];                  // [0:16) sum, [16:32) sumsq for oc = 16*half + j
#pragma unroll
    for (int i = 0; i < 32; i++) acc[i] = 0.f;

    int stride = gridDim.x * blockDim.x;
#pragma unroll 1
    for (int row = blockIdx.x * blockDim.x + tid; row < NROWS; row += stride) {
        float x0 = x[3*row], x1v = x[3*row+1], x2 = x[3*row+2];
#pragma unroll
        for (int i = 0; i < 8; i++) {
            int ic = ic0 + i;
            float wa = sw[3*ic], wb = sw[3*ic+1], wc = sw[3*ic+2], bias = sb[ic];
            float h0 = fmaxf(fmaf(wb, x0, fmaf(wc, x1v, bias)), 0.f);
            float h1 = fmaxf(fmaf(wa, x0, fmaf(wb, x1v, fmaf(wc, x2, bias))), 0.f);
            float h2 = fmaxf(fmaf(wa, x1v, fmaf(wb, x2, bias)), 0.f);
#pragma unroll
            for (int d = 0; d < 2; d++) {
                int oc = 2*ic + d;          // in [16*half, 16*half+16)
                int j  = 2*i + d;           // local accumulator index 0..15
                float u0 = sw2[3*oc], ub = sw2[3*oc+1], uc = sw2[3*oc+2];
                float t0 = fmaxf(fmaf(ub, h0, fmaf(uc, h1, sd2[3*oc+0])), 0.f);
                float t1 = fmaxf(fmaf(u0, h0, fmaf(ub, h1,
                                 fmaf(uc, h2, sd2[3*oc+1]))), 0.f);
                float t2 = fmaxf(fmaf(u0, h1, fmaf(ub, h2, sd2[3*oc+2])), 0.f);
                acc[j]      += t0 + t1 + t2;
                acc[16 + j] += t0*t0 + t1*t1 + t2*t2;
            }
        }
    }

    int lane = tid & 31, warp = tid >> 5;
#pragma unroll
    for (int i = 0; i < 32; i++) {
        float v = acc[i];
#pragma unroll
        for (int o = 16; o; o >>= 1) v += __shfl_down_sync(0xffffffffu, v, o);
        if (lane == 0) red[warp * 32 + i] = v;
    }
    __syncthreads();
    if (tid < 32) {
        float v = 0.f;
#pragma unroll
        for (int w = 0; w < 8; w++) v += red[w * 32 + tid];
        int base = 16 * half;
        if (tid < 16) atomicAdd(&g_acc2[base + tid], v);
        else          atomicAdd(&g_acc2[32 + base + (tid - 16)], v);
    }
}

// ------- finalize 2: BN2 params, fold (BN2 + mean/3) into FC1 -------
__global__ void finalize2_kernel(const float* __restrict__ g2, const float* __restrict__ bt2,
                                 const float* __restrict__ fw1, const float* __restrict__ fb1) {
    __shared__ float a2s[32], c2s[32];   // a2s holds a2/3
    int t = threadIdx.x;  // 512 threads
    const float inv = 1.f / (3.f * (float)NROWS);
    if (t < 32) {
        float m   = g_acc2[t] * inv;
        float var = g_acc2[32 + t] * inv - m * m;
        float a   = g2[t] * rsqrtf(var + 1e-5f);
        a2s[t] = a * (1.f / 3.f);
        c2s[t] = bt2[t] - m * a;
    }
    __syncthreads();
    g_fw1f[t] = fw1[t] * a2s[t & 31];    // row-major [j*32 + oc], scaled per oc
    if (t < 16) {
        float s = fb1[t];
#pragma unroll
        for (int c = 0; c < 32; c++) s = fmaf(fw1[t*32 + c], c2s[c], s);
        g_fb1f[t] = s;
    }
}

// ---------------- pass 3: full fused forward (two-stage, spill-free) ----------------
__global__ void __launch_bounds__(256) pass3_kernel(const float* __restrict__ x,
                                                    const float* __restrict__ w1,
                                                    const float* __restrict__ b1,
                                                    const float* __restrict__ fw2,
                                                    const float* __restrict__ fb2,
                                                    float* __restrict__ out) {
    __shared__ __align__(16) float4 scw1[16];     // (wa,wb,wc,bias) per ic
    __shared__ __align__(16) float4 scw2a[32];    // (u0,ub,uc,d0) per oc
    __shared__ __align__(16) float4 scw2b[32];    // (d1,d2,-,-) per oc
    __shared__ __align__(16) float sfw1[512];     // [j*32+oc]
    __shared__ float sfb1[16], sfw2[16];
    __shared__ float s_sh[256 * 33];              // per-thread s[32], pad 33
    int tid = threadIdx.x;
    if (tid < 16) {
        scw1[tid] = make_float4(w1[3*tid], w1[3*tid+1], w1[3*tid+2], b1[tid]);
        sfb1[tid] = g_fb1f[tid];
        sfw2[tid] = fw2[tid];
    }
    if (tid < 32) {
        scw2a[tid] = make_float4(g_w2f[3*tid], g_w2f[3*tid+1], g_w2f[3*tid+2], g_d2[3*tid]);
        scw2b[tid] = make_float4(g_d2[3*tid+1], g_d2[3*tid+2], 0.f, 0.f);
    }
    for (int i = tid; i < 512; i += blockDim.x) sfw1[i] = g_fw1f[i];
    __syncthreads();
    const float fb2v = fb2[0];

    int row = blockIdx.x * blockDim.x + tid;      // grid sized to exactly NROWS
    float x0 = x[3*row], x1v = x[3*row+1], x2 = x[3*row+2];
    float* myS = &s_sh[tid * 33];

    // ---- stage 1: conv1 -> relu -> (BN1-folded) conv2 -> relu -> pooled sums ----
#pragma unroll 1
    for (int ic = 0; ic < 16; ic++) {
        float4 w = scw1[ic];
        float h0 = fmaxf(fmaf(w.y, x0, fmaf(w.z, x1v, w.w)), 0.f);
        float h1 = fmaxf(fmaf(w.x, x0, fmaf(w.y, x1v, fmaf(w.z, x2, w.w))), 0.f);
        float h2 = fmaxf(fmaf(w.x, x1v, fmaf(w.y, x2, w.w)), 0.f);
#pragma unroll
        for (int d = 0; d < 2; d++) {
            int oc = 2*ic + d;
            float4 ua = scw2a[oc];
            float4 ub4 = scw2b[oc];
            float t0 = fmaxf(fmaf(ua.y, h0, fmaf(ua.z, h1, ua.w)), 0.f);
            float t1 = fmaxf(fmaf(ua.x, h0, fmaf(ua.y, h1,
                             fmaf(ua.z, h2, ub4.x))), 0.f);
            float t2 = fmaxf(fmaf(ua.x, h1, fmaf(ua.y, h2, ub4.y)), 0.f);
            myS[oc] = t0 + t1 + t2;
        }
    }

    // ---- stage 2: FC1 (folded BN2+mean) + relu + FC2 ----
    float sv[32];
#pragma unroll
    for (int oc = 0; oc < 32; oc++) sv[oc] = myS[oc];

    float o = fb2v;
#pragma unroll 1
    for (int j = 0; j < 16; j++) {
        float fj = sfb1[j];
#pragma unroll
        for (int q = 0; q < 8; q++) {
            float4 w = *reinterpret_cast<const float4*>(&sfw1[j*32 + 4*q]);
            fj = fmaf(w.x, sv[4*q + 0], fj);
            fj = fmaf(w.y, sv[4*q + 1], fj);
            fj = fmaf(w.z, sv[4*q + 2], fj);
            fj = fmaf(w.w, sv[4*q + 3], fj);
        }
        o = fmaf(sfw2[j], fmaxf(fj, 0.f), o);
    }
    out[row] = o;
}

extern "C" void kernel_launch(void* const* d_in, const int* in_sizes, int n_in,
                              void* d_out, int out_size) {
    const float* x   = (const float*)d_in[0];
    const float* w1  = (const float*)d_in[1];
    const float* b1  = (const float*)d_in[2];
    const float* g1  = (const float*)d_in[3];
    const float* bt1 = (const float*)d_in[4];
    const float* w2  = (const float*)d_in[5];
    const float* b2  = (const float*)d_in[6];
    const float* g2  = (const float*)d_in[7];
    const float* bt2 = (const float*)d_in[8];
    const float* fw1 = (const float*)d_in[9];
    const float* fb1 = (const float*)d_in[10];
    const float* fw2 = (const float*)d_in[11];
    const float* fb2 = (const float*)d_in[12];
    float* out = (float*)d_out;

    zero_kernel<<<1, 64>>>();
    pass1_kernel<<<1024, 256>>>(x, w1, b1);
    finalize1_kernel<<<1, 32>>>(g1, bt1, w2, b2);
    dim3 g2d(1024, 2);
    pass2_kernel<<<g2d, 256>>>(x, w1, b1);
    finalize2_kernel<<<1, 512>>>(g2, bt2, fw1, fb1);
    pass3_kernel<<<NROWS / 256, 256>>>(x, w1, b1, fw2, fb2, out);
}

// round 5
// speedup vs baseline: 8.0053x; 1.2819x over previous
#include <cuda_runtime.h>

#define NROWS (1 << 20)

// ---- device-global scratch ----
__device__ float g_acc1[32];    // [0:16) sum, [16:32) sumsq of relu(conv1)
__device__ float g_acc2[64];    // [0:32) sum, [32:64) sumsq of relu(conv2)
__device__ float g_w2f[96];     // BN1-folded conv2 weights  [oc*3 + k]
__device__ float g_d2[96];      // folded conv2 bias table   [oc*3 + t]
__device__ float g_fw1f[512];   // BN2+mean-folded fc1 weights [j*32 + oc]
__device__ float g_fb1f[16];    // folded fc1 bias

// ---- packed f32x2 helpers ----
union F2U { float2 f; unsigned long long u; };
__device__ __forceinline__ float2 ffma2(float2 a, float2 b, float2 c) {
    F2U ua, ub, uc, r; ua.f = a; ub.f = b; uc.f = c;
    asm("fma.rn.f32x2 %0, %1, %2, %3;" : "=l"(r.u) : "l"(ua.u), "l"(ub.u), "l"(uc.u));
    return r.f;
}
__device__ __forceinline__ float2 fadd2(float2 a, float2 b) {
    F2U ua, ub, r; ua.f = a; ub.f = b;
    asm("add.rn.f32x2 %0, %1, %2;" : "=l"(r.u) : "l"(ua.u), "l"(ub.u));
    return r.f;
}
__device__ __forceinline__ float2 relu2(float2 a) {
    return make_float2(fmaxf(a.x, 0.f), fmaxf(a.y, 0.f));
}

__global__ void zero_kernel() {
    int t = threadIdx.x;
    if (t < 32) g_acc1[t] = 0.f;
    if (t < 64) g_acc2[t] = 0.f;
}

// ------- pass 1: stats of relu(conv1+b1); blockIdx.y picks 8-channel half -------
__global__ void __launch_bounds__(256) pass1_kernel(const float* __restrict__ x,
                                                    const float* __restrict__ w1,
                                                    const float* __restrict__ b1) {
    __shared__ float sw[48], sb[16];
    __shared__ float red[8 * 16];
    int tid = threadIdx.x;
    int p = blockIdx.y;            // 0 or 1
    if (tid < 48) sw[tid] = w1[tid];
    if (tid < 16) sb[tid] = b1[tid];
    __syncthreads();

    const int ic0 = 8 * p;
    float acc[16];                 // [0:8) sum, [8:16) sumsq for ic0+j
#pragma unroll
    for (int i = 0; i < 16; i++) acc[i] = 0.f;

    const int stride = gridDim.x * blockDim.x;   // 131072
#pragma unroll 1
    for (int row = blockIdx.x * blockDim.x + tid; row < NROWS; row += 2 * stride) {
        int rowB = row + stride;
        float a0 = x[3*row], a1 = x[3*row+1], a2 = x[3*row+2];
        float c0 = x[3*rowB], c1 = x[3*rowB+1], c2 = x[3*rowB+2];
#pragma unroll
        for (int j = 0; j < 8; j++) {
            int c = ic0 + j;
            float wa = sw[3*c], wb = sw[3*c+1], wc = sw[3*c+2], bias = sb[c];
            // row A
            float h0 = fmaxf(fmaf(wb, a0, fmaf(wc, a1, bias)), 0.f);
            float h1 = fmaxf(fmaf(wa, a0, fmaf(wb, a1, fmaf(wc, a2, bias))), 0.f);
            float h2 = fmaxf(fmaf(wa, a1, fmaf(wb, a2, bias)), 0.f);
            acc[j]     += h0 + h1 + h2;
            acc[8 + j] += h0*h0 + h1*h1 + h2*h2;
            // row B
            float k0 = fmaxf(fmaf(wb, c0, fmaf(wc, c1, bias)), 0.f);
            float k1 = fmaxf(fmaf(wa, c0, fmaf(wb, c1, fmaf(wc, c2, bias))), 0.f);
            float k2 = fmaxf(fmaf(wa, c1, fmaf(wb, c2, bias)), 0.f);
            acc[j]     += k0 + k1 + k2;
            acc[8 + j] += k0*k0 + k1*k1 + k2*k2;
        }
    }

    int lane = tid & 31, warp = tid >> 5;
#pragma unroll
    for (int i = 0; i < 16; i++) {
        float v = acc[i];
#pragma unroll
        for (int o = 16; o; o >>= 1) v += __shfl_down_sync(0xffffffffu, v, o);
        if (lane == 0) red[warp * 16 + i] = v;
    }
    __syncthreads();
    if (tid < 16) {
        float v = 0.f;
#pragma unroll
        for (int w = 0; w < 8; w++) v += red[w * 16 + tid];
        if (tid < 8) atomicAdd(&g_acc1[ic0 + tid], v);
        else         atomicAdd(&g_acc1[16 + ic0 + (tid - 8)], v);
    }
}

// ------------- finalize 1: BN1 params, fold into conv2 -------------
__global__ void finalize1_kernel(const float* __restrict__ g1, const float* __restrict__ bt1,
                                 const float* __restrict__ w2, const float* __restrict__ b2) {
    __shared__ float a1s[16], c1s[16];
    int t = threadIdx.x;
    const float inv = 1.f / (3.f * (float)NROWS);
    if (t < 16) {
        float m   = g_acc1[t] * inv;
        float var = g_acc1[16 + t] * inv - m * m;
        float a   = g1[t] * rsqrtf(var + 1e-5f);
        a1s[t] = a;
        c1s[t] = bt1[t] - m * a;
    }
    __syncthreads();
    if (t < 32) {
        int ic = t >> 1;
        float a = a1s[ic], c = c1s[ic];
        float w0 = w2[3*t], wb = w2[3*t+1], wc = w2[3*t+2];
        g_w2f[3*t+0] = w0 * a;
        g_w2f[3*t+1] = wb * a;
        g_w2f[3*t+2] = wc * a;
        float bb = b2[t];
        g_d2[3*t+0] = bb + c * (wb + wc);        // t=0: taps k=1,2 in-bounds
        g_d2[3*t+1] = bb + c * (w0 + wb + wc);   // t=1: all taps
        g_d2[3*t+2] = bb + c * (w0 + wb);        // t=2: taps k=0,1 in-bounds
    }
}

// ------- pass 2: stats of relu(conv2(bn1)+b2); blockIdx.y picks 4-ic quarter -------
__global__ void __launch_bounds__(256) pass2_kernel(const float* __restrict__ x,
                                                    const float* __restrict__ w1,
                                                    const float* __restrict__ b1) {
    __shared__ float sw[48], sb[16], sw2[96], sd2[96];
    __shared__ float red[8 * 16];
    int tid = threadIdx.x;
    int q = blockIdx.y;            // 0..3
    if (tid < 48) sw[tid] = w1[tid];
    if (tid < 16) sb[tid] = b1[tid];
    if (tid < 96) { sw2[tid] = g_w2f[tid]; sd2[tid] = g_d2[tid]; }
    __syncthreads();

    const int ic0 = 4 * q;         // input channels [ic0, ic0+4) -> oc [8q, 8q+8)
    float acc[16];                 // [0:8) sum, [8:16) sumsq
#pragma unroll
    for (int i = 0; i < 16; i++) acc[i] = 0.f;

    const int stride = gridDim.x * blockDim.x;   // 131072
#pragma unroll 1
    for (int row = blockIdx.x * blockDim.x + tid; row < NROWS; row += 2 * stride) {
        int rowB = row + stride;
        float a0 = x[3*row], a1 = x[3*row+1], a2 = x[3*row+2];
        float c0 = x[3*rowB], c1 = x[3*rowB+1], c2 = x[3*rowB+2];
#pragma unroll
        for (int rr = 0; rr < 2; rr++) {
            float x0 = rr ? c0 : a0, x1v = rr ? c1 : a1, x2 = rr ? c2 : a2;
#pragma unroll
            for (int i = 0; i < 4; i++) {
                int ic = ic0 + i;
                float wa = sw[3*ic], wb = sw[3*ic+1], wc = sw[3*ic+2], bias = sb[ic];
                float h0 = fmaxf(fmaf(wb, x0, fmaf(wc, x1v, bias)), 0.f);
                float h1 = fmaxf(fmaf(wa, x0, fmaf(wb, x1v, fmaf(wc, x2, bias))), 0.f);
                float h2 = fmaxf(fmaf(wa, x1v, fmaf(wb, x2, bias)), 0.f);
#pragma unroll
                for (int d = 0; d < 2; d++) {
                    int oc = 2*ic + d;
                    int j  = 2*i + d;
                    float u0 = sw2[3*oc], ub = sw2[3*oc+1], uc = sw2[3*oc+2];
                    float t0 = fmaxf(fmaf(ub, h0, fmaf(uc, h1, sd2[3*oc+0])), 0.f);
                    float t1 = fmaxf(fmaf(u0, h0, fmaf(ub, h1,
                                     fmaf(uc, h2, sd2[3*oc+1]))), 0.f);
                    float t2 = fmaxf(fmaf(u0, h1, fmaf(ub, h2, sd2[3*oc+2])), 0.f);
                    acc[j]     += t0 + t1 + t2;
                    acc[8 + j] += t0*t0 + t1*t1 + t2*t2;
                }
            }
        }
    }

    int lane = tid & 31, warp = tid >> 5;
#pragma unroll
    for (int i = 0; i < 16; i++) {
        float v = acc[i];
#pragma unroll
        for (int o = 16; o; o >>= 1) v += __shfl_down_sync(0xffffffffu, v, o);
        if (lane == 0) red[warp * 16 + i] = v;
    }
    __syncthreads();
    if (tid < 16) {
        float v = 0.f;
#pragma unroll
        for (int w = 0; w < 8; w++) v += red[w * 16 + tid];
        int base = 8 * q;
        if (tid < 8) atomicAdd(&g_acc2[base + tid], v);
        else         atomicAdd(&g_acc2[32 + base + (tid - 8)], v);
    }
}

// ------- finalize 2: BN2 params, fold (BN2 + mean/3) into FC1 -------
__global__ void finalize2_kernel(const float* __restrict__ g2, const float* __restrict__ bt2,
                                 const float* __restrict__ fw1, const float* __restrict__ fb1) {
    __shared__ float a2s[32], c2s[32];   // a2s holds a2/3
    int t = threadIdx.x;  // 512 threads
    const float inv = 1.f / (3.f * (float)NROWS);
    if (t < 32) {
        float m   = g_acc2[t] * inv;
        float var = g_acc2[32 + t] * inv - m * m;
        float a   = g2[t] * rsqrtf(var + 1e-5f);
        a2s[t] = a * (1.f / 3.f);
        c2s[t] = bt2[t] - m * a;
    }
    __syncthreads();
    g_fw1f[t] = fw1[t] * a2s[t & 31];    // row-major [j*32 + oc], scaled per oc
    if (t < 16) {
        float s = fb1[t];
#pragma unroll
        for (int c = 0; c < 32; c++) s = fmaf(fw1[t*32 + c], c2s[c], s);
        g_fb1f[t] = s;
    }
}

// ---------------- pass 3: fused forward, 2 rows/thread, f32x2 packed ----------------
__global__ void __launch_bounds__(256) pass3_kernel(const float* __restrict__ x,
                                                    const float* __restrict__ w1,
                                                    const float* __restrict__ b1,
                                                    const float* __restrict__ fw2,
                                                    const float* __restrict__ fb2,
                                                    float* __restrict__ out) {
    __shared__ __align__(16) float2 sc1[16 * 4];   // per ic: dup(wa),dup(wb),dup(wc),dup(bias)
    __shared__ __align__(16) float2 sc2[32 * 6];   // per oc: dup(u0,ub,uc,d0,d1,d2)
    __shared__ __align__(16) float2 sfw[32 * 16];  // dup fc1 folded, transposed [oc*16+j]
    __shared__ float sfb1[16], sfw2[16];
    int tid = threadIdx.x;
    if (tid < 16) {
        sc1[4*tid+0] = make_float2(w1[3*tid],   w1[3*tid]);
        sc1[4*tid+1] = make_float2(w1[3*tid+1], w1[3*tid+1]);
        sc1[4*tid+2] = make_float2(w1[3*tid+2], w1[3*tid+2]);
        sc1[4*tid+3] = make_float2(b1[tid],     b1[tid]);
        sfb1[tid] = g_fb1f[tid];
        sfw2[tid] = fw2[tid];
    }
    if (tid < 32) {
#pragma unroll
        for (int k = 0; k < 3; k++) {
            sc2[6*tid+k]   = make_float2(g_w2f[3*tid+k], g_w2f[3*tid+k]);
            sc2[6*tid+3+k] = make_float2(g_d2[3*tid+k],  g_d2[3*tid+k]);
        }
    }
    for (int i = tid; i < 512; i += blockDim.x) {
        int oc = i >> 4, j = i & 15;
        float v = g_fw1f[j * 32 + oc];
        sfw[i] = make_float2(v, v);
    }
    __syncthreads();
    const float fb2v = fb2[0];

    int g = blockIdx.x * blockDim.x + tid;       // pair index; grid covers NROWS/2
    const float2* xx = reinterpret_cast<const float2*>(x);
    float2 p0 = xx[3*g], p1 = xx[3*g+1], p2 = xx[3*g+2];
    // rows A=2g, B=2g+1; lanes = (A, B)
    float2 X0 = make_float2(p0.x, p1.y);
    float2 X1 = make_float2(p0.y, p2.x);
    float2 X2 = make_float2(p1.x, p2.y);

    float2 f[16];
#pragma unroll
    for (int j = 0; j < 16; j++) f[j] = make_float2(sfb1[j], sfb1[j]);

#pragma unroll 1
    for (int ic = 0; ic < 16; ic++) {
        const float2* c1 = &sc1[ic * 4];
        float2 wa = c1[0], wb = c1[1], wc = c1[2], bi = c1[3];
        float2 h0 = relu2(ffma2(wb, X0, ffma2(wc, X1, bi)));
        float2 h1 = relu2(ffma2(wa, X0, ffma2(wb, X1, ffma2(wc, X2, bi))));
        float2 h2 = relu2(ffma2(wa, X1, ffma2(wb, X2, bi)));
#pragma unroll
        for (int d = 0; d < 2; d++) {
            int oc = 2*ic + d;
            const float2* c2 = &sc2[oc * 6];
            float2 u0 = c2[0], ub = c2[1], uc = c2[2];
            float2 d0 = c2[3], d1 = c2[4], d2v = c2[5];
            float2 t0 = relu2(ffma2(ub, h0, ffma2(uc, h1, d0)));
            float2 t1 = relu2(ffma2(u0, h0, ffma2(ub, h1, ffma2(uc, h2, d1))));
            float2 t2 = relu2(ffma2(u0, h1, ffma2(ub, h2, d2v)));
            float2 s = fadd2(fadd2(t0, t1), t2);
            const float2* wv = &sfw[oc * 16];
#pragma unroll
            for (int j = 0; j < 16; j++) f[j] = ffma2(wv[j], s, f[j]);
        }
    }

    float oA = fb2v, oB = fb2v;
#pragma unroll
    for (int j = 0; j < 16; j++) {
        float wj = sfw2[j];
        oA = fmaf(wj, fmaxf(f[j].x, 0.f), oA);
        oB = fmaf(wj, fmaxf(f[j].y, 0.f), oB);
    }
    reinterpret_cast<float2*>(out)[g] = make_float2(oA, oB);
}

extern "C" void kernel_launch(void* const* d_in, const int* in_sizes, int n_in,
                              void* d_out, int out_size) {
    const float* x   = (const float*)d_in[0];
    const float* w1  = (const float*)d_in[1];
    const float* b1  = (const float*)d_in[2];
    const float* g1  = (const float*)d_in[3];
    const float* bt1 = (const float*)d_in[4];
    const float* w2  = (const float*)d_in[5];
    const float* b2  = (const float*)d_in[6];
    const float* g2  = (const float*)d_in[7];
    const float* bt2 = (const float*)d_in[8];
    const float* fw1 = (const float*)d_in[9];
    const float* fb1 = (const float*)d_in[10];
    const float* fw2 = (const float*)d_in[11];
    const float* fb2 = (const float*)d_in[12];
    float* out = (float*)d_out;

    zero_kernel<<<1, 64>>>();
    dim3 g1d(512, 2);
    pass1_kernel<<<g1d, 256>>>(x, w1, b1);
    finalize1_kernel<<<1, 32>>>(g1, bt1, w2, b2);
    dim3 g2d(512, 4);
    pass2_kernel<<<g2d, 256>>>(x, w1, b1);
    finalize2_kernel<<<1, 512>>>(g2, bt2, fw1, fb1);
    pass3_kernel<<<NROWS / 512, 256>>>(x, w1, b1, fw2, fb2, out);
}